// round 11
// baseline (speedup 1.0000x reference)
#include <cuda_runtime.h>
#include <math.h>

#define TOLC   0.5f
#define RESC   0.03f
#define GPTS   4000
#define BATCH  128
#define NEV    64
#define HEV    128
#define NTHR   256
#define NQUART 4
#define GSUB   (GPTS / NQUART)       // 1000 grid points per block
#define PER_T  4                     // chunk = 4 points = 0.12 time units
#define NBLK   (BATCH * NQUART)      // 512
#define NLCH   250                   // local chunks per block
#define INV_CHUNKW (1.0f / 0.12f)

#define LOG2E_F  1.4426950408889634f
#define LN2_F    0.6931471805599453f
#define E_ZERO  (-100000)
#define FXSCALE  1073741824.0        // 2^30

#define NSLOT  32
#define SLOTSTRIDE 16                // 128B between slots

__device__ unsigned long long g_accs[NSLOT * SLOTSTRIDE];
__device__ unsigned int g_cnt = 0;

// ---- branchless fixed-trip lower_bound (n = 64) ----
__device__ __forceinline__ int lb64(const float* __restrict__ a, float x) {
    int lo = 0;
    #pragma unroll
    for (int s = 32; s >= 1; s >>= 1)
        if (a[lo + s - 1] < x) lo += s;
    if (a[lo] < x) lo += 1;
    return lo;
}

// (m, e) pair: value = m * 2^e with m in [1,2), or m==0 (zero)
__device__ __forceinline__ void pair_add(float& am, int& ae, float bm, int be) {
    if (bm == 0.f) return;
    if (am == 0.f) { am = bm; ae = be; return; }
    int d = ae - be;
    float m; int e;
    if (d >= 0) { m = am + ldexpf(bm, -d); e = ae; }
    else        { m = bm + ldexpf(am,  d); e = be; }
    if (m >= 2.f) { m *= 0.5f; e += 1; }
    am = m; ae = e;
}

__device__ __forceinline__ float pair_log2(float m, int e) {
    return (m > 0.f) ? ((float)e + __log2f(m)) : -INFINITY;
}

__device__ __forceinline__ void pair_from_log2(float x, float& m, int& e) {
    float n = floorf(x);
    m = exp2f(x - n); e = (int)n;
    if (m >= 2.f) { m *= 0.5f; e += 1; }
}

__device__ __forceinline__ float warp_sum(float v) {
    v += __shfl_down_sync(0xffffffffu, v, 16);
    v += __shfl_down_sync(0xffffffffu, v, 8);
    v += __shfl_down_sync(0xffffffffu, v, 4);
    v += __shfl_down_sync(0xffffffffu, v, 2);
    v += __shfl_down_sync(0xffffffffu, v, 1);
    return v;
}

__device__ __forceinline__ long long warp_sum_ll(long long v) {
    #pragma unroll
    for (int off = 16; off >= 1; off >>= 1)
        v += __shfl_down_sync(0xffffffffu, v, off);
    return v;
}

__global__ __launch_bounds__(NTHR)
void llm_fused_kernel(const float* __restrict__ times0, const int* __restrict__ states0,
                      const float* __restrict__ times1, const int* __restrict__ states1,
                      const float* __restrict__ head_times, const int* __restrict__ head_states,
                      const float* __restrict__ base_p, const float* __restrict__ weights,
                      float* __restrict__ out)
{
    const int b = blockIdx.x >> 2;       // batch
    const int q = blockIdx.x & 3;        // quarter
    const int t = threadIdx.x;
    const int lane = t & 31;
    const int wrp  = t >> 5;
    const int qlo  = q * NLCH;           // first global chunk of this quarter

    __shared__ float sh_t0[NEV], sh_t1[NEV], sh_ht[HEV];
    __shared__ float sh_eff[HEV];
    __shared__ float sh_P0[NEV + 1];
    __shared__ float sh_L0[NEV + 1], sh_L1[NEV + 1];
    __shared__ int   sh_cs[NTHR];        // packed per-local-chunk counts
    __shared__ int   sh_basec;           // packed counts of events before this quarter
    __shared__ int   sh_wtot[8];
    __shared__ float red[NTHR / 32];
    __shared__ bool  amLast;

    sh_cs[t] = 0;
    if (t == 0) sh_basec = 0;
    if (t >= 64 && t < 192) {
        const int j = t - 64;
        sh_ht[j]  = head_times[b * HEV + j];
        sh_eff[j] = (head_states[b * HEV + j] == 0) ? 1.f : -1.f;
    }
    __syncthreads();

    // ============ prologue (warp 0) || histogram (warps 1-7) ============
    if (t < 32) {
        const int j0 = 2 * lane, j1 = j0 + 1;
        const float2 T0 = ((const float2*)(times0 + b * NEV))[lane];
        const int2   S0 = ((const int2*)(states0 + b * NEV))[lane];
        const float2 T1 = ((const float2*)(times1 + b * NEV))[lane];
        const int2   S1 = ((const int2*)(states1 + b * NEV))[lane];
        sh_t0[j0] = T0.x; sh_t0[j1] = T0.y;
        sh_t1[j0] = T1.x; sh_t1[j1] = T1.y;

        const float w0 = weights[0], w1 = weights[1];
        const float mw = fmaxf(w0, w1);
        const float ew0 = __expf(w0 - mw), ew1 = __expf(w1 - mw);
        const float inv = 1.f / (ew0 + ew1);
        const float lw0 = __log2f(ew0 * inv);
        const float lw1 = __log2f(ew1 * inv);

        // phase A: dual scans of exp(t0) masked by s0
        float x0m, x1m; int x0e, x1e;
        pair_from_log2(T0.x * LOG2E_F, x0m, x0e);
        pair_from_log2(T0.y * LOG2E_F, x1m, x1e);
        float a0m = (S0.x == 1) ? x0m : 0.f;  int a0e = (S0.x == 1) ? x0e : E_ZERO;
        float a1m = (S0.y == 1) ? x1m : 0.f;  int a1e = (S0.y == 1) ? x1e : E_ZERO;
        float b0m = (S0.x == 0) ? x0m : 0.f;  int b0e = (S0.x == 0) ? x0e : E_ZERO;
        float b1m = (S0.y == 0) ? x1m : 0.f;  int b1e = (S0.y == 0) ? x1e : E_ZERO;
        float pam = a0m; int pae = a0e; pair_add(pam, pae, a1m, a1e);
        float pbm = b0m; int pbe = b0e; pair_add(pbm, pbe, b1m, b1e);
        #pragma unroll
        for (int off = 1; off < 32; off <<= 1) {
            float oam = __shfl_up_sync(0xffffffffu, pam, off);
            int   oae = __shfl_up_sync(0xffffffffu, pae, off);
            float obm = __shfl_up_sync(0xffffffffu, pbm, off);
            int   obe = __shfl_up_sync(0xffffffffu, pbe, off);
            if (lane >= off) { pair_add(pam, pae, oam, oae); pair_add(pbm, pbe, obm, obe); }
        }
        float sam = __shfl_up_sync(0xffffffffu, pam, 1);
        int   sae = __shfl_up_sync(0xffffffffu, pae, 1);
        float sbm = __shfl_up_sync(0xffffffffu, pbm, 1);
        int   sbe = __shfl_up_sync(0xffffffffu, pbe, 1);
        if (lane == 0) { sam = 0.f; sae = E_ZERO; sbm = 0.f; sbe = E_ZERO; }
        float ia_m = sam; int ia_e = sae; pair_add(ia_m, ia_e, a0m, a0e);
        float ib_m = sbm; int ib_e = sbe; pair_add(ib_m, ib_e, b0m, b0e);
        sh_P0[j0 + 1] = pair_log2(ia_m, ia_e);
        sh_P0[j1 + 1] = pair_log2(pam, pae);
        sh_L1[j0 + 1] = pair_log2(ib_m, ib_e) + lw1;
        sh_L1[j1 + 1] = pair_log2(pbm, pbe) + lw1;
        if (lane == 0) { sh_P0[0] = -INFINITY; sh_L1[0] = -INFINITY; sh_L0[0] = -INFINITY; }
        __syncwarp();

        // phase B: ps0_j = exp(t1_j) * P0[c_j]
        float c0m = 0.f; int c0e = E_ZERO;
        if (S1.x == 1) {
            const int cj = lb64(sh_t0, T1.x - TOLC);
            const float p = sh_P0[cj];
            if (p > -INFINITY) pair_from_log2(T1.x * LOG2E_F + p, c0m, c0e);
        }
        float c1m = 0.f; int c1e = E_ZERO;
        if (S1.y == 1) {
            const int cj = lb64(sh_t0, T1.y - TOLC);
            const float p = sh_P0[cj];
            if (p > -INFINITY) pair_from_log2(T1.y * LOG2E_F + p, c1m, c1e);
        }
        // phase C: scan -> L0
        float pcm = c0m; int pce = c0e; pair_add(pcm, pce, c1m, c1e);
        #pragma unroll
        for (int off = 1; off < 32; off <<= 1) {
            float ocm = __shfl_up_sync(0xffffffffu, pcm, off);
            int   oce = __shfl_up_sync(0xffffffffu, pce, off);
            if (lane >= off) pair_add(pcm, pce, ocm, oce);
        }
        float scm = __shfl_up_sync(0xffffffffu, pcm, 1);
        int   sce = __shfl_up_sync(0xffffffffu, pce, 1);
        if (lane == 0) { scm = 0.f; sce = E_ZERO; }
        float ic_m = scm; int ic_e = sce; pair_add(ic_m, ic_e, c0m, c0e);
        sh_L0[j0 + 1] = pair_log2(ic_m, ic_e) + lw0;
        sh_L0[j1 + 1] = pair_log2(pcm, pce) + lw0;
    } else if (t >= 64 && t < 128) {
        // histogram: times1 activation chunks (conservative; fixup walk corrects)
        const float v = times1[b * NEV + (t - 64)];
        const int a = __float2int_rd((v + TOLC) * INV_CHUNKW) + 2;
        const int la = a - qlo;
        if (la < 0) atomicAdd(&sh_basec, 1);
        else if (la < NLCH) atomicAdd(&sh_cs[la], 1);
    } else if (t >= 128 && t < 192) {
        const float v = times0[b * NEV + (t - 128)];
        const int a = __float2int_rd((v + TOLC) * INV_CHUNKW) + 2;
        const int la = a - qlo;
        if (la < 0) atomicAdd(&sh_basec, 1 << 8);
        else if (la < NLCH) atomicAdd(&sh_cs[la], 1 << 8);
    } else if (t >= 32 && t < 64) {
        const float v = head_times[b * HEV + (t - 32)];
        const int a = __float2int_rd(v * INV_CHUNKW) + 2;
        const int la = a - qlo;
        if (la < 0) atomicAdd(&sh_basec, 1 << 16);
        else if (la < NLCH) atomicAdd(&sh_cs[la], 1 << 16);
    } else if (t >= 192) {
        const float v = head_times[b * HEV + (t - 192 + 64)];
        const int a = __float2int_rd(v * INV_CHUNKW) + 2;
        const int la = a - qlo;
        if (la < 0) atomicAdd(&sh_basec, 1 << 16);
        else if (la < NLCH) atomicAdd(&sh_cs[la], 1 << 16);
    }
    const float base = base_p[0];
    __syncthreads();

    // ============ packed inclusive block scan of chunk counts ============
    int pc = sh_cs[t];
    #pragma unroll
    for (int off = 1; off < 32; off <<= 1) {
        int ov = __shfl_up_sync(0xffffffffu, pc, off);
        if (lane >= off) pc += ov;
    }
    if (lane == 31) sh_wtot[wrp] = pc;
    __syncthreads();
    if (t < 8) {
        int wv = sh_wtot[t];
        #pragma unroll
        for (int off = 1; off < 8; off <<= 1) {
            int ov = __shfl_up_sync(0xffu, wv, off);
            if (lane >= off) wv += ov;
        }
        sh_wtot[t] = wv;
    }
    __syncthreads();
    const int cs = pc + ((wrp > 0) ? sh_wtot[wrp - 1] : 0) + sh_basec;

    // ================= grid evaluation: this block's quarter ==============
    float lamsum = 0.f;
    if (t < NLCH) {
        const int gbeg = (qlo + t) * PER_T;
        float te  = (float)gbeg * RESC;
        float thr = te - TOLC;
        int c   = cs & 255;
        int c1  = (cs >> 8) & 255;
        int cnt = (cs >> 16) & 255;
        // entry fixup walks (counts understated by construction)
        float nt1 = (c   < NEV) ? sh_t1[c]   : 1e30f;
        while (nt1 < thr) { c++;  nt1 = (c  < NEV) ? sh_t1[c]  : 1e30f; }
        float nt0 = (c1  < NEV) ? sh_t0[c1]  : 1e30f;
        while (nt0 < thr) { c1++; nt0 = (c1 < NEV) ? sh_t0[c1] : 1e30f; }
        float nht = (cnt < HEV) ? sh_ht[cnt] : 1e30f;
        while (nht < te)  { cnt++; nht = (cnt < HEV) ? sh_ht[cnt] : 1e30f; }

        float f0  = __expf(fmaf(LN2_F, sh_L0[c],  -2.f * te));
        float f1  = __expf(fmaf(LN2_F, sh_L1[c1], -te));
        float eff0 = sh_eff[(cnt + HEV - 1) & (HEV - 1)];
        const float d2 = 0.886920437f;   // exp(-2*RES)
        const float d1 = 0.970445527f;   // exp(-RES)

        #pragma unroll
        for (int g = gbeg; g < gbeg + PER_T; ++g) {
            if (g > gbeg) {
                te  = (float)g * RESC;
                thr = te - TOLC;
                f0 *= d2;
                f1 *= d1;
                if (nt1 < thr || nt0 < thr || nht < te) {   // rare slow path
                    while (nt1 < thr) { c++;  nt1 = (c  < NEV) ? sh_t1[c]  : 1e30f; }
                    while (nt0 < thr) { c1++; nt0 = (c1 < NEV) ? sh_t0[c1] : 1e30f; }
                    while (nht < te)  { cnt++; nht = (cnt < HEV) ? sh_ht[cnt] : 1e30f; }
                    f0 = __expf(fmaf(LN2_F, sh_L0[c],  -2.f * te));
                    f1 = __expf(fmaf(LN2_F, sh_L1[c1], -te));
                    eff0 = sh_eff[(cnt + HEV - 1) & (HEV - 1)];
                }
            }
            lamsum += __expf(fmaf(eff0, f0 - f1, base));
        }
    }

    // ---- event points on warp 7: ev = q*32 + lane, cnt(ht[ev]) == ev ----
    float logsum = 0.f;
    if (t >= 224) {
        const int ev = q * 32 + lane;
        if (ev >= 1) {
            const float te  = sh_ht[ev];
            const float thr = te - TOLC;
            const int c   = lb64(sh_t1, thr);
            const int c1  = lb64(sh_t0, thr);
            const float feat0 = __expf(fmaf(LN2_F, sh_L0[c],  -2.f * te));
            const float feat1 = __expf(fmaf(LN2_F, sh_L1[c1], -te));
            logsum = fmaf(sh_eff[ev - 1], feat0 - feat1, base);
        }
    }

    // ======= reduce: block -> fixed-point atomic, 32 spread slots =========
    float pv = warp_sum(logsum - RESC * lamsum);
    if (lane == 0) red[wrp] = pv;
    __syncthreads();
    if (t < 32) {
        float s = (t < NTHR / 32) ? red[t] : 0.f;
        s = warp_sum(s);
        if (t == 0) {
            long long iq = llrint((double)s * FXSCALE);
            const int slot = (blockIdx.x & (NSLOT - 1)) * SLOTSTRIDE;
            atomicAdd(&g_accs[slot], (unsigned long long)iq);
            __threadfence();
            unsigned int prev = atomicAdd(&g_cnt, 1u);
            amLast = (prev == (unsigned int)(NBLK - 1));
        }
    }
    __syncthreads();

    // ---- last block: sum the 32 slots (warp 0), reset for replay ----
    if (amLast && t < 32) {
        __threadfence();
        unsigned long long myv = atomicAdd(&g_accs[t * SLOTSTRIDE], 0ull);
        long long tot = warp_sum_ll((long long)myv);
        if (t == 0) {
            out[0] = (float)((double)tot * (1.0 / FXSCALE));
        }
        g_accs[t * SLOTSTRIDE] = 0ull;
        if (t == 0) {
            __threadfence();
            g_cnt = 0u;
        }
    }
}

extern "C" void kernel_launch(void* const* d_in, const int* in_sizes, int n_in,
                              void* d_out, int out_size)
{
    const float* times0      = (const float*)d_in[0];
    const int*   states0     = (const int*)  d_in[1];
    const float* times1      = (const float*)d_in[2];
    const int*   states1     = (const int*)  d_in[3];
    const float* head_times  = (const float*)d_in[4];
    const int*   head_states = (const int*)  d_in[5];
    const float* base_p      = (const float*)d_in[6];
    const float* weights     = (const float*)d_in[7];
    float* out = (float*)d_out;

    llm_fused_kernel<<<NBLK, NTHR>>>(times0, states0, times1, states1,
                                     head_times, head_states, base_p, weights, out);
}

// round 12
// speedup vs baseline: 1.1600x; 1.1600x over previous
#include <cuda_runtime.h>
#include <math.h>

#define TOLC   0.5f
#define RESC   0.03f
#define GPTS   4000
#define BATCH  128
#define NEV    64
#define HEV    128
#define NTHR   256
#define NQUART 4
#define GSUB   (GPTS / NQUART)     // 1000 grid points per block
#define PER_T  4                   // 250 active threads * 4 = 1000
#define NBLK   (BATCH * NQUART)    // 512

#define LOG2E_F  1.4426950408889634f
#define LN2_F    0.6931471805599453f
#define E_ZERO  (-100000)
#define FXSCALE  1073741824.0      // 2^30

#define NSLOT  32
#define SLOTSTRIDE 16              // 128B between slots

__device__ unsigned long long g_accs[NSLOT * SLOTSTRIDE];
__device__ unsigned int g_cnt = 0;

__device__ __forceinline__ float ex2f(float x) {
    float r;
    asm("ex2.approx.ftz.f32 %0, %1;" : "=f"(r) : "f"(x));
    return r;
}

// ---- branchless fixed-trip lower_bound (n = 64 / 128) ----
__device__ __forceinline__ int lb64(const float* __restrict__ a, float x) {
    int lo = 0;
    #pragma unroll
    for (int s = 32; s >= 1; s >>= 1)
        if (a[lo + s - 1] < x) lo += s;
    if (a[lo] < x) lo += 1;
    return lo;
}
__device__ __forceinline__ int lb128(const float* __restrict__ a, float x) {
    int lo = 0;
    #pragma unroll
    for (int s = 64; s >= 1; s >>= 1)
        if (a[lo + s - 1] < x) lo += s;
    if (a[lo] < x) lo += 1;
    return lo;
}

// (m, e) pair: value = m * 2^e with m in [1,2), or m==0 (zero)
__device__ __forceinline__ void pair_add(float& am, int& ae, float bm, int be) {
    if (bm == 0.f) return;
    if (am == 0.f) { am = bm; ae = be; return; }
    int d = ae - be;
    float m; int e;
    if (d >= 0) { m = am + ldexpf(bm, -d); e = ae; }
    else        { m = bm + ldexpf(am,  d); e = be; }
    if (m >= 2.f) { m *= 0.5f; e += 1; }
    am = m; ae = e;
}

__device__ __forceinline__ float pair_log2(float m, int e) {
    return (m > 0.f) ? ((float)e + __log2f(m)) : -INFINITY;
}

__device__ __forceinline__ void pair_from_log2(float x, float& m, int& e) {
    float n = floorf(x);
    m = exp2f(x - n); e = (int)n;
    if (m >= 2.f) { m *= 0.5f; e += 1; }
}

__device__ __forceinline__ float warp_sum(float v) {
    v += __shfl_down_sync(0xffffffffu, v, 16);
    v += __shfl_down_sync(0xffffffffu, v, 8);
    v += __shfl_down_sync(0xffffffffu, v, 4);
    v += __shfl_down_sync(0xffffffffu, v, 2);
    v += __shfl_down_sync(0xffffffffu, v, 1);
    return v;
}

__device__ __forceinline__ long long warp_sum_ll(long long v) {
    #pragma unroll
    for (int off = 16; off >= 1; off >>= 1)
        v += __shfl_down_sync(0xffffffffu, v, off);
    return v;
}

__global__ __launch_bounds__(NTHR, 4)
void llm_fused_kernel(const float* __restrict__ times0, const int* __restrict__ states0,
                      const float* __restrict__ times1, const int* __restrict__ states1,
                      const float* __restrict__ head_times, const int* __restrict__ head_states,
                      const float* __restrict__ base_p, const float* __restrict__ weights,
                      float* __restrict__ out)
{
    const int b = blockIdx.x >> 2;       // batch
    const int q = blockIdx.x & 3;        // quarter
    const int t = threadIdx.x;
    const int lane = t & 31;
    const int wrp  = t >> 5;

    __shared__ float sh_t0[NEV], sh_t1[NEV], sh_ht[HEV];
    __shared__ float sh_eff[HEV];
    __shared__ float sh_P0[NEV + 1];
    __shared__ float sh_L0[NEV + 1], sh_L1[NEV + 1];   // log2 tables; wn*log2e folded
    __shared__ float red[NTHR / 32];
    __shared__ bool amLast;

    // ---- warps 2-5 load head arrays in parallel with warp-0 prologue ----
    if (t >= 64 && t < 192) {
        const int j = t - 64;
        sh_ht[j]  = head_times[b * HEV + j];
        sh_eff[j] = (head_states[b * HEV + j] == 0) ? 1.f : -1.f;
    }

    // ================= prologue: warp 0 only, barrier-free =================
    if (t < 32) {
        const int j0 = 2 * lane, j1 = j0 + 1;
        const float2 T0 = ((const float2*)(times0 + b * NEV))[lane];
        const int2   S0 = ((const int2*)(states0 + b * NEV))[lane];
        const float2 T1 = ((const float2*)(times1 + b * NEV))[lane];
        const int2   S1 = ((const int2*)(states1 + b * NEV))[lane];
        sh_t0[j0] = T0.x; sh_t0[j1] = T0.y;
        sh_t1[j0] = T1.x; sh_t1[j1] = T1.y;

        const float w0 = weights[0], w1 = weights[1];
        const float mw = fmaxf(w0, w1);
        const float ew0 = __expf(w0 - mw), ew1 = __expf(w1 - mw);
        const float inv = 1.f / (ew0 + ew1);
        // fold wn * log2e into the tables (eval works fully in log2 space)
        const float lw0 = __log2f(ew0 * inv * LOG2E_F);
        const float lw1 = __log2f(ew1 * inv * LOG2E_F);

        // phase A: dual scans of exp(t0) masked by s0
        float x0m, x1m; int x0e, x1e;
        pair_from_log2(T0.x * LOG2E_F, x0m, x0e);
        pair_from_log2(T0.y * LOG2E_F, x1m, x1e);
        float a0m = (S0.x == 1) ? x0m : 0.f;  int a0e = (S0.x == 1) ? x0e : E_ZERO;
        float a1m = (S0.y == 1) ? x1m : 0.f;  int a1e = (S0.y == 1) ? x1e : E_ZERO;
        float b0m = (S0.x == 0) ? x0m : 0.f;  int b0e = (S0.x == 0) ? x0e : E_ZERO;
        float b1m = (S0.y == 0) ? x1m : 0.f;  int b1e = (S0.y == 0) ? x1e : E_ZERO;
        float pam = a0m; int pae = a0e; pair_add(pam, pae, a1m, a1e);
        float pbm = b0m; int pbe = b0e; pair_add(pbm, pbe, b1m, b1e);
        #pragma unroll
        for (int off = 1; off < 32; off <<= 1) {
            float oam = __shfl_up_sync(0xffffffffu, pam, off);
            int   oae = __shfl_up_sync(0xffffffffu, pae, off);
            float obm = __shfl_up_sync(0xffffffffu, pbm, off);
            int   obe = __shfl_up_sync(0xffffffffu, pbe, off);
            if (lane >= off) { pair_add(pam, pae, oam, oae); pair_add(pbm, pbe, obm, obe); }
        }
        float sam = __shfl_up_sync(0xffffffffu, pam, 1);
        int   sae = __shfl_up_sync(0xffffffffu, pae, 1);
        float sbm = __shfl_up_sync(0xffffffffu, pbm, 1);
        int   sbe = __shfl_up_sync(0xffffffffu, pbe, 1);
        if (lane == 0) { sam = 0.f; sae = E_ZERO; sbm = 0.f; sbe = E_ZERO; }
        float ia_m = sam; int ia_e = sae; pair_add(ia_m, ia_e, a0m, a0e);
        float ib_m = sbm; int ib_e = sbe; pair_add(ib_m, ib_e, b0m, b0e);
        sh_P0[j0 + 1] = pair_log2(ia_m, ia_e);
        sh_P0[j1 + 1] = pair_log2(pam, pae);
        sh_L1[j0 + 1] = pair_log2(ib_m, ib_e) + lw1;
        sh_L1[j1 + 1] = pair_log2(pbm, pbe) + lw1;
        if (lane == 0) { sh_P0[0] = -INFINITY; sh_L1[0] = -INFINITY; sh_L0[0] = -INFINITY; }
        __syncwarp();

        // phase B: ps0_j = exp(t1_j) * P0[c_j]
        float c0m = 0.f; int c0e = E_ZERO;
        if (S1.x == 1) {
            const int cj = lb64(sh_t0, T1.x - TOLC);
            const float p = sh_P0[cj];
            if (p > -INFINITY) pair_from_log2(T1.x * LOG2E_F + p, c0m, c0e);
        }
        float c1m = 0.f; int c1e = E_ZERO;
        if (S1.y == 1) {
            const int cj = lb64(sh_t0, T1.y - TOLC);
            const float p = sh_P0[cj];
            if (p > -INFINITY) pair_from_log2(T1.y * LOG2E_F + p, c1m, c1e);
        }
        // phase C: scan -> L0
        float pcm = c0m; int pce = c0e; pair_add(pcm, pce, c1m, c1e);
        #pragma unroll
        for (int off = 1; off < 32; off <<= 1) {
            float ocm = __shfl_up_sync(0xffffffffu, pcm, off);
            int   oce = __shfl_up_sync(0xffffffffu, pce, off);
            if (lane >= off) pair_add(pcm, pce, ocm, oce);
        }
        float scm = __shfl_up_sync(0xffffffffu, pcm, 1);
        int   sce = __shfl_up_sync(0xffffffffu, pce, 1);
        if (lane == 0) { scm = 0.f; sce = E_ZERO; }
        float ic_m = scm; int ic_e = sce; pair_add(ic_m, ic_e, c0m, c0e);
        sh_L0[j0 + 1] = pair_log2(ic_m, ic_e) + lw0;
        sh_L0[j1 + 1] = pair_log2(pcm, pce) + lw0;
    }
    const float base  = base_p[0];
    const float base2 = base * LOG2E_F;
    __syncthreads();

    // ================= grid evaluation: this block's quarter ===============
    // lambda = 2^(base2 + f0 - f1), f0/f1 carry eff0 * wn * log2e folded.
    float lamsum = 0.f;
    const int gbeg = q * GSUB + t * PER_T;
    if (t * PER_T < GSUB) {
        float te  = (float)gbeg * RESC;
        const float thr0 = te - TOLC;
        int c   = lb64(sh_t1, thr0);
        int c1  = lb64(sh_t0, thr0);
        int cnt = lb128(sh_ht, te);
        float nt1 = (c   < NEV) ? sh_t1[c]   : 1e30f;
        float nt0 = (c1  < NEV) ? sh_t0[c1]  : 1e30f;
        float nht = (cnt < HEV) ? sh_ht[cnt] : 1e30f;
        float eff0 = sh_eff[(cnt + HEV - 1) & (HEV - 1)];
        float f0 = eff0 * ex2f(fmaf(-2.f * LOG2E_F, te, sh_L0[c]));
        float f1 = eff0 * ex2f(fmaf(-LOG2E_F, te, sh_L1[c1]));
        float nxt = fminf(fminf(nt1, nt0) + TOLC, nht);
        const float d2 = 0.886920437f;   // exp(-2*RES)
        const float d1 = 0.970445527f;   // exp(-RES)

        #pragma unroll
        for (int k = 0; k < PER_T; ++k) {
            if (k > 0) {
                te += RESC;
                f0 *= d2;
                f1 *= d1;
                if (te > nxt) {                       // rare slow path
                    const float thr = te - TOLC;
                    while (nt1 < thr) { c++;  nt1 = (c  < NEV) ? sh_t1[c]  : 1e30f; }
                    while (nt0 < thr) { c1++; nt0 = (c1 < NEV) ? sh_t0[c1] : 1e30f; }
                    while (nht < te)  { cnt++; nht = (cnt < HEV) ? sh_ht[cnt] : 1e30f; }
                    eff0 = sh_eff[(cnt + HEV - 1) & (HEV - 1)];
                    f0 = eff0 * ex2f(fmaf(-2.f * LOG2E_F, te, sh_L0[c]));
                    f1 = eff0 * ex2f(fmaf(-LOG2E_F, te, sh_L1[c1]));
                    nxt = fminf(fminf(nt1, nt0) + TOLC, nht);
                }
            }
            lamsum += ex2f((base2 + f0) - f1);
        }
    }

    // ---- event points on warp 7: ev = q*32 + lane, cnt(ht[ev]) == ev ----
    float logsum = 0.f;
    if (t >= 224) {
        const int ev = q * 32 + lane;
        if (ev >= 1) {
            const float te  = sh_ht[ev];
            const float thr = te - TOLC;
            const int c   = lb64(sh_t1, thr);
            const int c1  = lb64(sh_t0, thr);
            const float F0 = ex2f(fmaf(-2.f * LOG2E_F, te, sh_L0[c]));
            const float F1 = ex2f(fmaf(-LOG2E_F, te, sh_L1[c1]));
            // log(lam) = base + eff * ln2 * (F0 - F1)
            logsum = fmaf(sh_eff[ev - 1] * LN2_F, F0 - F1, base);
        }
    }

    // ======= reduce: block -> fixed-point atomic, 32 spread slots =========
    float pv = warp_sum(logsum - RESC * lamsum);
    if (lane == 0) red[wrp] = pv;
    __syncthreads();
    if (t < 32) {
        float s = (t < NTHR / 32) ? red[t] : 0.f;
        s = warp_sum(s);
        if (t == 0) {
            long long iq = llrint((double)s * FXSCALE);
            const int slot = (blockIdx.x & (NSLOT - 1)) * SLOTSTRIDE;
            atomicAdd(&g_accs[slot], (unsigned long long)iq);
            __threadfence();
            unsigned int prev = atomicAdd(&g_cnt, 1u);
            amLast = (prev == (unsigned int)(NBLK - 1));
        }
    }
    __syncthreads();

    // ---- last block: sum the 32 slots (warp 0), reset for replay ----
    if (amLast && t < 32) {
        __threadfence();
        unsigned long long myv = atomicAdd(&g_accs[t * SLOTSTRIDE], 0ull);
        long long tot = warp_sum_ll((long long)myv);
        if (t == 0) {
            out[0] = (float)((double)tot * (1.0 / FXSCALE));
        }
        g_accs[t * SLOTSTRIDE] = 0ull;
        if (t == 0) {
            __threadfence();
            g_cnt = 0u;
        }
    }
}

extern "C" void kernel_launch(void* const* d_in, const int* in_sizes, int n_in,
                              void* d_out, int out_size)
{
    const float* times0      = (const float*)d_in[0];
    const int*   states0     = (const int*)  d_in[1];
    const float* times1      = (const float*)d_in[2];
    const int*   states1     = (const int*)  d_in[3];
    const float* head_times  = (const float*)d_in[4];
    const int*   head_states = (const int*)  d_in[5];
    const float* base_p      = (const float*)d_in[6];
    const float* weights     = (const float*)d_in[7];
    float* out = (float*)d_out;

    llm_fused_kernel<<<NBLK, NTHR>>>(times0, states0, times1, states1,
                                     head_times, head_states, base_p, weights, out);
}

// round 13
// speedup vs baseline: 1.1629x; 1.0025x over previous
#include <cuda_runtime.h>
#include <math.h>

#define TOLC   0.5f
#define RESC   0.03f
#define GPTS   4000
#define BATCH  128
#define NEV    64
#define HEV    128
#define NTHR   256
#define NQUART 4
#define GSUB   (GPTS / NQUART)     // 1000 grid points per block
#define PER_T  4                   // 250 active threads * 4 = 1000
#define NBLK   (BATCH * NQUART)    // 512

#define LOG2E_F  1.4426950408889634f
#define LN2_F    0.6931471805599453f
#define E_ZERO  (-100000)
#define FXSCALE  1073741824.0      // 2^30

#define NSLOT  32
#define SLOTSTRIDE 16              // 128B between slots

__device__ unsigned long long g_accs[NSLOT * SLOTSTRIDE];
__device__ unsigned int g_cnt = 0;

__device__ __forceinline__ float ex2f(float x) {
    float r;
    asm("ex2.approx.ftz.f32 %0, %1;" : "=f"(r) : "f"(x));
    return r;
}

// ---- branchless fixed-trip lower_bound (n = 64 / 128) ----
__device__ __forceinline__ int lb64(const float* __restrict__ a, float x) {
    int lo = 0;
    #pragma unroll
    for (int s = 32; s >= 1; s >>= 1)
        if (a[lo + s - 1] < x) lo += s;
    if (a[lo] < x) lo += 1;
    return lo;
}
__device__ __forceinline__ int lb128(const float* __restrict__ a, float x) {
    int lo = 0;
    #pragma unroll
    for (int s = 64; s >= 1; s >>= 1)
        if (a[lo + s - 1] < x) lo += s;
    if (a[lo] < x) lo += 1;
    return lo;
}

// (m, e) pair: value = m * 2^e with m in [1,2), or m==0 (zero)
__device__ __forceinline__ void pair_add(float& am, int& ae, float bm, int be) {
    if (bm == 0.f) return;
    if (am == 0.f) { am = bm; ae = be; return; }
    int d = ae - be;
    float m; int e;
    if (d >= 0) { m = am + ldexpf(bm, -d); e = ae; }
    else        { m = bm + ldexpf(am,  d); e = be; }
    if (m >= 2.f) { m *= 0.5f; e += 1; }
    am = m; ae = e;
}

__device__ __forceinline__ float pair_log2(float m, int e) {
    return (m > 0.f) ? ((float)e + __log2f(m)) : -INFINITY;
}

__device__ __forceinline__ void pair_from_log2(float x, float& m, int& e) {
    float n = floorf(x);
    m = exp2f(x - n); e = (int)n;
    if (m >= 2.f) { m *= 0.5f; e += 1; }
}

__device__ __forceinline__ float warp_sum(float v) {
    v += __shfl_down_sync(0xffffffffu, v, 16);
    v += __shfl_down_sync(0xffffffffu, v, 8);
    v += __shfl_down_sync(0xffffffffu, v, 4);
    v += __shfl_down_sync(0xffffffffu, v, 2);
    v += __shfl_down_sync(0xffffffffu, v, 1);
    return v;
}

__device__ __forceinline__ long long warp_sum_ll(long long v) {
    #pragma unroll
    for (int off = 16; off >= 1; off >>= 1)
        v += __shfl_down_sync(0xffffffffu, v, off);
    return v;
}

__global__ __launch_bounds__(NTHR, 4)
void llm_fused_kernel(const float* __restrict__ times0, const int* __restrict__ states0,
                      const float* __restrict__ times1, const int* __restrict__ states1,
                      const float* __restrict__ head_times, const int* __restrict__ head_states,
                      const float* __restrict__ base_p, const float* __restrict__ weights,
                      float* __restrict__ out)
{
    const int b = blockIdx.x >> 2;       // batch
    const int q = blockIdx.x & 3;        // quarter
    const int t = threadIdx.x;
    const int lane = t & 31;
    const int wrp  = t >> 5;

    __shared__ float sh_t0[NEV], sh_t1[NEV], sh_ht[HEV];
    __shared__ float sh_eff[HEV];
    __shared__ float sh_P0[NEV + 1];
    __shared__ float sh_L0[NEV + 1], sh_L1[NEV + 1];   // log2 tables; wn*log2e folded
    __shared__ float red[NTHR / 32];
    __shared__ bool amLast;

    // ---- warps 2-5 load head arrays in parallel with warp-0 prologue ----
    if (t >= 64 && t < 192) {
        const int j = t - 64;
        sh_ht[j]  = head_times[b * HEV + j];
        sh_eff[j] = (head_states[b * HEV + j] == 0) ? 1.f : -1.f;
    }

    // ================= prologue: warp 0 only, barrier-free =================
    if (t < 32) {
        const int j0 = 2 * lane, j1 = j0 + 1;
        const float2 T0 = ((const float2*)(times0 + b * NEV))[lane];
        const int2   S0 = ((const int2*)(states0 + b * NEV))[lane];
        const float2 T1 = ((const float2*)(times1 + b * NEV))[lane];
        const int2   S1 = ((const int2*)(states1 + b * NEV))[lane];
        sh_t0[j0] = T0.x; sh_t0[j1] = T0.y;
        sh_t1[j0] = T1.x; sh_t1[j1] = T1.y;

        const float w0 = weights[0], w1 = weights[1];
        const float mw = fmaxf(w0, w1);
        const float ew0 = __expf(w0 - mw), ew1 = __expf(w1 - mw);
        const float inv = 1.f / (ew0 + ew1);
        const float lw0 = __log2f(ew0 * inv * LOG2E_F);
        const float lw1 = __log2f(ew1 * inv * LOG2E_F);

        // phase A: dual scans of exp(t0) masked by s0
        float x0m, x1m; int x0e, x1e;
        pair_from_log2(T0.x * LOG2E_F, x0m, x0e);
        pair_from_log2(T0.y * LOG2E_F, x1m, x1e);
        float a0m = (S0.x == 1) ? x0m : 0.f;  int a0e = (S0.x == 1) ? x0e : E_ZERO;
        float a1m = (S0.y == 1) ? x1m : 0.f;  int a1e = (S0.y == 1) ? x1e : E_ZERO;
        float b0m = (S0.x == 0) ? x0m : 0.f;  int b0e = (S0.x == 0) ? x0e : E_ZERO;
        float b1m = (S0.y == 0) ? x1m : 0.f;  int b1e = (S0.y == 0) ? x1e : E_ZERO;
        float pam = a0m; int pae = a0e; pair_add(pam, pae, a1m, a1e);
        float pbm = b0m; int pbe = b0e; pair_add(pbm, pbe, b1m, b1e);
        #pragma unroll
        for (int off = 1; off < 32; off <<= 1) {
            float oam = __shfl_up_sync(0xffffffffu, pam, off);
            int   oae = __shfl_up_sync(0xffffffffu, pae, off);
            float obm = __shfl_up_sync(0xffffffffu, pbm, off);
            int   obe = __shfl_up_sync(0xffffffffu, pbe, off);
            if (lane >= off) { pair_add(pam, pae, oam, oae); pair_add(pbm, pbe, obm, obe); }
        }
        float sam = __shfl_up_sync(0xffffffffu, pam, 1);
        int   sae = __shfl_up_sync(0xffffffffu, pae, 1);
        float sbm = __shfl_up_sync(0xffffffffu, pbm, 1);
        int   sbe = __shfl_up_sync(0xffffffffu, pbe, 1);
        if (lane == 0) { sam = 0.f; sae = E_ZERO; sbm = 0.f; sbe = E_ZERO; }
        float ia_m = sam; int ia_e = sae; pair_add(ia_m, ia_e, a0m, a0e);
        float ib_m = sbm; int ib_e = sbe; pair_add(ib_m, ib_e, b0m, b0e);
        sh_P0[j0 + 1] = pair_log2(ia_m, ia_e);
        sh_P0[j1 + 1] = pair_log2(pam, pae);
        sh_L1[j0 + 1] = pair_log2(ib_m, ib_e) + lw1;
        sh_L1[j1 + 1] = pair_log2(pbm, pbe) + lw1;
        if (lane == 0) { sh_P0[0] = -INFINITY; sh_L1[0] = -INFINITY; sh_L0[0] = -INFINITY; }
        __syncwarp();

        // phase B: ps0_j = exp(t1_j) * P0[c_j]
        float c0m = 0.f; int c0e = E_ZERO;
        if (S1.x == 1) {
            const int cj = lb64(sh_t0, T1.x - TOLC);
            const float p = sh_P0[cj];
            if (p > -INFINITY) pair_from_log2(T1.x * LOG2E_F + p, c0m, c0e);
        }
        float c1m = 0.f; int c1e = E_ZERO;
        if (S1.y == 1) {
            const int cj = lb64(sh_t0, T1.y - TOLC);
            const float p = sh_P0[cj];
            if (p > -INFINITY) pair_from_log2(T1.y * LOG2E_F + p, c1m, c1e);
        }
        // phase C: scan -> L0
        float pcm = c0m; int pce = c0e; pair_add(pcm, pce, c1m, c1e);
        #pragma unroll
        for (int off = 1; off < 32; off <<= 1) {
            float ocm = __shfl_up_sync(0xffffffffu, pcm, off);
            int   oce = __shfl_up_sync(0xffffffffu, pce, off);
            if (lane >= off) pair_add(pcm, pce, ocm, oce);
        }
        float scm = __shfl_up_sync(0xffffffffu, pcm, 1);
        int   sce = __shfl_up_sync(0xffffffffu, pce, 1);
        if (lane == 0) { scm = 0.f; sce = E_ZERO; }
        float ic_m = scm; int ic_e = sce; pair_add(ic_m, ic_e, c0m, c0e);
        sh_L0[j0 + 1] = pair_log2(ic_m, ic_e) + lw0;
        sh_L0[j1 + 1] = pair_log2(pcm, pce) + lw0;
    }
    const float base  = base_p[0];
    const float base2 = base * LOG2E_F;
    __syncthreads();

    // ================= grid evaluation: this block's quarter ===============
    // lambda = 2^(base2 + f0 - f1), f0/f1 carry eff0 * wn * log2e folded.
    float lamsum = 0.f;
    const int gbeg = q * GSUB + t * PER_T;
    if (t * PER_T < GSUB) {
        float te  = (float)gbeg * RESC;
        const float thr0 = te - TOLC;
        int c   = lb64(sh_t1, thr0);
        int c1  = lb64(sh_t0, thr0);
        int cnt = lb128(sh_ht, te);
        float nt1 = (c   < NEV) ? sh_t1[c]   : 1e30f;
        float nt0 = (c1  < NEV) ? sh_t0[c1]  : 1e30f;
        float nht = (cnt < HEV) ? sh_ht[cnt] : 1e30f;
        float eff0 = sh_eff[(cnt + HEV - 1) & (HEV - 1)];
        float f0 = eff0 * ex2f(fmaf(-2.f * LOG2E_F, te, sh_L0[c]));
        float f1 = eff0 * ex2f(fmaf(-LOG2E_F, te, sh_L1[c1]));
        float nxt = fminf(fminf(nt1, nt0) + TOLC, nht);
        const float d2 = 0.886920437f;   // exp(-2*RES)
        const float d1 = 0.970445527f;   // exp(-RES)

        if (te + (PER_T - 1) * RESC <= nxt) {
            // ---------- fast path: whole chunk event-free, straight-line ----------
            const float a0 = (base2 + f0) - f1;
            const float g0 = f0 * d2,        h0 = f1 * d1;
            const float g1 = g0 * d2,        h1 = h0 * d1;
            const float g2 = g1 * d2,        h2 = h1 * d1;
            const float l0 = ex2f(a0);
            const float l1 = ex2f((base2 + g0) - h0);
            const float l2 = ex2f((base2 + g1) - h1);
            const float l3 = ex2f((base2 + g2) - h2);
            lamsum += (l0 + l1) + (l2 + l3);
        } else {
            // ---------- slow path: per-point careful loop ----------
            #pragma unroll
            for (int k = 0; k < PER_T; ++k) {
                if (k > 0) {
                    te += RESC;
                    f0 *= d2;
                    f1 *= d1;
                    if (te > nxt) {
                        const float thr = te - TOLC;
                        while (nt1 < thr) { c++;  nt1 = (c  < NEV) ? sh_t1[c]  : 1e30f; }
                        while (nt0 < thr) { c1++; nt0 = (c1 < NEV) ? sh_t0[c1] : 1e30f; }
                        while (nht < te)  { cnt++; nht = (cnt < HEV) ? sh_ht[cnt] : 1e30f; }
                        eff0 = sh_eff[(cnt + HEV - 1) & (HEV - 1)];
                        f0 = eff0 * ex2f(fmaf(-2.f * LOG2E_F, te, sh_L0[c]));
                        f1 = eff0 * ex2f(fmaf(-LOG2E_F, te, sh_L1[c1]));
                        nxt = fminf(fminf(nt1, nt0) + TOLC, nht);
                    }
                }
                lamsum += ex2f((base2 + f0) - f1);
            }
        }
    }

    // ---- event points on warp 7: ev = q*32 + lane, cnt(ht[ev]) == ev ----
    float logsum = 0.f;
    if (t >= 224) {
        const int ev = q * 32 + lane;
        if (ev >= 1) {
            const float te  = sh_ht[ev];
            const float thr = te - TOLC;
            const int c   = lb64(sh_t1, thr);
            const int c1  = lb64(sh_t0, thr);
            const float F0 = ex2f(fmaf(-2.f * LOG2E_F, te, sh_L0[c]));
            const float F1 = ex2f(fmaf(-LOG2E_F, te, sh_L1[c1]));
            logsum = fmaf(sh_eff[ev - 1] * LN2_F, F0 - F1, base);
        }
    }

    // ======= reduce: block -> fixed-point atomic, 32 spread slots =========
    float pv = warp_sum(logsum - RESC * lamsum);
    if (lane == 0) red[wrp] = pv;
    __syncthreads();
    if (t < 32) {
        float s = (t < NTHR / 32) ? red[t] : 0.f;
        s = warp_sum(s);
        if (t == 0) {
            long long iq = llrint((double)s * FXSCALE);
            const int slot = (blockIdx.x & (NSLOT - 1)) * SLOTSTRIDE;
            atomicAdd(&g_accs[slot], (unsigned long long)iq);
            __threadfence();
            unsigned int prev = atomicAdd(&g_cnt, 1u);
            amLast = (prev == (unsigned int)(NBLK - 1));
        }
    }
    __syncthreads();

    // ---- last block: sum the 32 slots (warp 0), reset for replay ----
    if (amLast && t < 32) {
        __threadfence();
        unsigned long long myv = atomicAdd(&g_accs[t * SLOTSTRIDE], 0ull);
        long long tot = warp_sum_ll((long long)myv);
        if (t == 0) {
            out[0] = (float)((double)tot * (1.0 / FXSCALE));
        }
        g_accs[t * SLOTSTRIDE] = 0ull;
        if (t == 0) {
            __threadfence();
            g_cnt = 0u;
        }
    }
}

extern "C" void kernel_launch(void* const* d_in, const int* in_sizes, int n_in,
                              void* d_out, int out_size)
{
    const float* times0      = (const float*)d_in[0];
    const int*   states0     = (const int*)  d_in[1];
    const float* times1      = (const float*)d_in[2];
    const int*   states1     = (const int*)  d_in[3];
    const float* head_times  = (const float*)d_in[4];
    const int*   head_states = (const int*)  d_in[5];
    const float* base_p      = (const float*)d_in[6];
    const float* weights     = (const float*)d_in[7];
    float* out = (float*)d_out;

    llm_fused_kernel<<<NBLK, NTHR>>>(times0, states0, times1, states1,
                                     head_times, head_states, base_p, weights, out);
}